// round 1
// baseline (speedup 1.0000x reference)
#include <cuda_runtime.h>

// Problem constants (shapes are fixed by the dataset):
// b=2, s=256, C=128, H=W=16, YH=XH=CH=2 -> nH=8 heads, c=64, h=w=8, D=c*h*w=4096
// mask: 16x16 token grid, radius-1 neighborhood (<=9 keys per query)

#define NTOK   512            // b*s
#define FDIM   4096           // per-head feature dim
#define SLICE  (256*4096)     // tokens*FDIM per (b,head)

// Scratch (device globals -- allocation-free per harness rules)
__device__ float g_q[2*8*256*4096];
__device__ float g_k[2*8*256*4096];
__device__ float g_v[2*8*256*4096];
__device__ float g_sa[512*128*256];

// ---------------------------------------------------------------------------
// Kernel A: QKV pointwise projection  qkv[d,p] = sum_c w_qkv[d,c]*seq[t,c,p]
// grid: (token 512, dtile 3 -> q/k/v, ptile 2), block 256.
// Each block: C[128,128] = W[128,128] * X[128,128], K=128.
// Epilogue scatters into per-head layout g_{q,k,v}[b][n][s][f].
// ---------------------------------------------------------------------------
__global__ __launch_bounds__(256) void qkv_gemm(const float* __restrict__ seq,
                                                const float* __restrict__ w_qkv) {
    const int t  = blockIdx.x;
    const int dt = blockIdx.y;   // 0=q, 1=k, 2=v
    const int pt = blockIdx.z;   // column tile (0..1)

    __shared__ float As[16][132];   // As[k][d], padded vs bank conflicts
    __shared__ float Bs[16][128];   // Bs[k][p]

    const int tid = threadIdx.x;
    const int tx  = tid & 15;       // 16 col groups
    const int ty  = tid >> 4;       // 16 row groups

    float acc[8][8];
    #pragma unroll
    for (int i = 0; i < 8; i++)
        #pragma unroll
        for (int j = 0; j < 8; j++) acc[i][j] = 0.f;

    const float* wbase = w_qkv + dt * 128 * 128;              // rows dtile*128..+128
    const float* xbase = seq + (size_t)t * 32768 + pt * 128;  // X[k][p] = xbase[k*256+p]

    for (int kk = 0; kk < 128; kk += 16) {
        // load W tile transposed: As[k][d]
        for (int i = tid; i < 128 * 16; i += 256) {
            int d = i >> 4, k = i & 15;
            As[k][d] = wbase[d * 128 + kk + k];
        }
        // load X tile: Bs[k][p] (coalesced)
        for (int i = tid; i < 16 * 128; i += 256) {
            int p = i & 127, k = i >> 7;
            Bs[k][p] = xbase[(kk + k) * 256 + p];
        }
        __syncthreads();

        #pragma unroll
        for (int k = 0; k < 16; k++) {
            float a[8], bb[8];
            #pragma unroll
            for (int i = 0; i < 8; i++) a[i] = As[k][ty * 8 + i];
            #pragma unroll
            for (int j = 0; j < 8; j++) bb[j] = Bs[k][tx * 8 + j];
            #pragma unroll
            for (int i = 0; i < 8; i++)
                #pragma unroll
                for (int j = 0; j < 8; j++) acc[i][j] += a[i] * bb[j];
        }
        __syncthreads();
    }

    // Epilogue: scatter into head layout.
    // d = dt*128 + dl ; dl = ch*64 + cidx.  p -> (H,W): H=ys*8+hy, W=xs*8+wx.
    // head n = (ys*2+xs)*2 + ch ; f = cidx*64 + hy*8 + wx.
    const int b_ = t >> 8, s_ = t & 255;
    const int p0 = pt * 128 + tx * 8;       // 8 consecutive p, no 16-boundary crossing
    const int Hi = p0 >> 4, Wi0 = p0 & 15;
    const int ys = Hi >> 3, hy = Hi & 7, xs = Wi0 >> 3;
    float* dst = (dt == 0) ? g_q : (dt == 1) ? g_k : g_v;

    #pragma unroll
    for (int i = 0; i < 8; i++) {
        const int dl = ty * 8 + i;
        const int ch = dl >> 6, cidx = dl & 63;
        const int n = (ys * 2 + xs) * 2 + ch;
        size_t base = ((size_t)((b_ * 8 + n) * 256 + s_)) * FDIM + cidx * 64 + hy * 8;
        float4 v0 = make_float4(acc[i][0], acc[i][1], acc[i][2], acc[i][3]);
        float4 v1 = make_float4(acc[i][4], acc[i][5], acc[i][6], acc[i][7]);
        *reinterpret_cast<float4*>(dst + base)     = v0;
        *reinterpret_cast<float4*>(dst + base + 4) = v1;
    }
}

// ---------------------------------------------------------------------------
// Kernel B: masked attention. One block (256 thr) per (b, head, query token).
// <=9 neighbor keys; dot over 4096, softmax, weighted sum of V.
// Writes sa in token-major [t][C][H*W] layout for the output GEMM.
// ---------------------------------------------------------------------------
__global__ __launch_bounds__(256) void attn_kernel() {
    const int idx = blockIdx.x;            // 0..4095
    const int i   = idx & 255;             // query token
    const int n   = (idx >> 8) & 7;        // head
    const int b_  = idx >> 11;             // batch
    const int tid = threadIdx.x;

    const size_t slice = (size_t)(b_ * 8 + n) * SLICE;
    const size_t qb    = slice + (size_t)i * FDIM;

    float qreg[16];
    #pragma unroll
    for (int t = 0; t < 16; t++) qreg[t] = g_q[qb + t * 256 + tid];

    // enumerate valid 3x3 neighbors on the 16x16 token grid
    const int iy = i >> 4, ix = i & 15;
    int jidx[9]; int nj = 0;
    for (int dy = -1; dy <= 1; dy++) {
        int jy = iy + dy; if (jy < 0 || jy > 15) continue;
        for (int dx = -1; dx <= 1; dx++) {
            int jx = ix + dx; if (jx < 0 || jx > 15) continue;
            jidx[nj++] = jy * 16 + jx;
        }
    }

    // partial dots (per-thread over its 16 strided features)
    float part[9];
    for (int jj = 0; jj < nj; jj++) {
        const float* kb = g_k + slice + (size_t)jidx[jj] * FDIM;
        float p = 0.f;
        #pragma unroll
        for (int t = 0; t < 16; t++) p += qreg[t] * kb[t * 256 + tid];
        part[jj] = p;
    }

    // block reduction: warp shuffle then cross-warp in smem
    __shared__ float red[9][8];
    __shared__ float sm[9];
    for (int jj = 0; jj < nj; jj++) {
        float v = part[jj];
        #pragma unroll
        for (int o = 16; o > 0; o >>= 1) v += __shfl_down_sync(0xffffffffu, v, o);
        if ((tid & 31) == 0) red[jj][tid >> 5] = v;
    }
    __syncthreads();
    if (tid < nj) {
        float s = 0.f;
        #pragma unroll
        for (int w = 0; w < 8; w++) s += red[tid][w];
        sm[tid] = s * 0.015625f;   // scale = 1/sqrt(4096)
    }
    __syncthreads();

    // softmax over the nj valid scores (replicated per-thread; cheap)
    float sc[9];
    float m = -1e30f;
    for (int jj = 0; jj < nj; jj++) { sc[jj] = sm[jj]; m = fmaxf(m, sc[jj]); }
    float sum = 0.f;
    for (int jj = 0; jj < nj; jj++) { sc[jj] = __expf(sc[jj] - m); sum += sc[jj]; }
    const float inv = 1.0f / sum;

    // weighted sum of V
    float facc[16];
    #pragma unroll
    for (int t = 0; t < 16; t++) facc[t] = 0.f;
    for (int jj = 0; jj < nj; jj++) {
        const float a = sc[jj] * inv;
        const float* vb = g_v + slice + (size_t)jidx[jj] * FDIM;
        #pragma unroll
        for (int t = 0; t < 16; t++) facc[t] += a * vb[t * 256 + tid];
    }

    // write sa in [token][C][H*W] layout (merge heads back)
    const int ch = n & 1, sp = n >> 1, ys = sp >> 1, xs = sp & 1;
    const size_t tok = (size_t)(b_ * 256 + i) * 32768;
    #pragma unroll
    for (int t = 0; t < 16; t++) {
        const int f = t * 256 + tid;
        const int cidx = f >> 6, rem = f & 63, hy = rem >> 3, wx = rem & 7;
        const int Cc = ch * 64 + cidx;
        const int HWp = (ys * 8 + hy) * 16 + xs * 8 + wx;
        g_sa[tok + (size_t)Cc * 256 + HWp] = facc[t];
    }
}

// ---------------------------------------------------------------------------
// Kernel C: output projection  out[d,p] = sum_c w_out[d,c]*sa[t,c,p] + b_out[d]
// grid: (token 512, ptile 2), block 256. Same GEMM core as kernel A.
// ---------------------------------------------------------------------------
__global__ __launch_bounds__(256) void out_gemm(const float* __restrict__ w_out,
                                                const float* __restrict__ b_out,
                                                float* __restrict__ out) {
    const int t  = blockIdx.x;
    const int pt = blockIdx.y;

    __shared__ float As[16][132];
    __shared__ float Bs[16][128];

    const int tid = threadIdx.x;
    const int tx  = tid & 15;
    const int ty  = tid >> 4;

    float acc[8][8];
    #pragma unroll
    for (int i = 0; i < 8; i++)
        #pragma unroll
        for (int j = 0; j < 8; j++) acc[i][j] = 0.f;

    const float* xbase = g_sa + (size_t)t * 32768 + pt * 128;

    for (int kk = 0; kk < 128; kk += 16) {
        for (int i = tid; i < 128 * 16; i += 256) {
            int d = i >> 4, k = i & 15;
            As[k][d] = w_out[d * 128 + kk + k];
        }
        for (int i = tid; i < 16 * 128; i += 256) {
            int p = i & 127, k = i >> 7;
            Bs[k][p] = xbase[(kk + k) * 256 + p];
        }
        __syncthreads();

        #pragma unroll
        for (int k = 0; k < 16; k++) {
            float a[8], bb[8];
            #pragma unroll
            for (int i = 0; i < 8; i++) a[i] = As[k][ty * 8 + i];
            #pragma unroll
            for (int j = 0; j < 8; j++) bb[j] = Bs[k][tx * 8 + j];
            #pragma unroll
            for (int i = 0; i < 8; i++)
                #pragma unroll
                for (int j = 0; j < 8; j++) acc[i][j] += a[i] * bb[j];
        }
        __syncthreads();
    }

    // coalesced epilogue + bias
    float* obase = out + (size_t)t * 32768 + pt * 128 + tx * 8;
    #pragma unroll
    for (int i = 0; i < 8; i++) {
        const int d = ty * 8 + i;
        const float bias = b_out[d];
        float4 v0 = make_float4(acc[i][0] + bias, acc[i][1] + bias,
                                acc[i][2] + bias, acc[i][3] + bias);
        float4 v1 = make_float4(acc[i][4] + bias, acc[i][5] + bias,
                                acc[i][6] + bias, acc[i][7] + bias);
        *reinterpret_cast<float4*>(obase + (size_t)d * 256)     = v0;
        *reinterpret_cast<float4*>(obase + (size_t)d * 256 + 4) = v1;
    }
}

extern "C" void kernel_launch(void* const* d_in, const int* in_sizes, int n_in,
                              void* d_out, int out_size) {
    const float* seq   = (const float*)d_in[0];
    const float* w_qkv = (const float*)d_in[1];
    const float* w_out = (const float*)d_in[2];
    const float* b_out = (const float*)d_in[3];
    // d_in[4], d_in[5] = n_sub_x, n_sub_y (fixed at 16; hardcoded)
    float* out = (float*)d_out;

    dim3 gA(NTOK, 3, 2);
    qkv_gemm<<<gA, 256>>>(seq, w_qkv);

    attn_kernel<<<4096, 256>>>();

    dim3 gC(NTOK, 2);
    out_gemm<<<gC, 256>>>(w_out, b_out, out);
}

// round 2
// speedup vs baseline: 1.6797x; 1.6797x over previous
#include <cuda_runtime.h>
#include <cstdint>

// Problem constants (fixed by dataset):
// b=2, s=256, C=128, H=W=16, YH=XH=CH=2 -> nH=8 heads, c=64, h=w=8, D=4096
// mask: 16x16 token grid, radius-1 neighborhood (<=9 keys per query)

#define NTOK   512
#define FDIM   4096
#define SLICE  (256*4096)

// Scratch (device globals -- allocation-free per harness rules)
__device__ float g_q[2*8*256*4096];
__device__ float g_k[2*8*256*4096];
__device__ float g_v[2*8*256*4096];
__device__ float g_sa[512*128*256];

// ---------------------------------------------------------------------------
// tf32 helpers
// ---------------------------------------------------------------------------
__device__ __forceinline__ uint32_t f2tf32(float x) {
    uint32_t r;
    asm("cvt.rna.tf32.f32 %0, %1;" : "=r"(r) : "f"(x));
    return r;
}

__device__ __forceinline__ void mma_tf32(float* c,
                                         uint32_t a0, uint32_t a1, uint32_t a2, uint32_t a3,
                                         uint32_t b0, uint32_t b1) {
    asm volatile(
        "mma.sync.aligned.m16n8k8.row.col.f32.tf32.tf32.f32 "
        "{%0,%1,%2,%3}, {%4,%5,%6,%7}, {%8,%9}, {%0,%1,%2,%3};"
        : "+f"(c[0]), "+f"(c[1]), "+f"(c[2]), "+f"(c[3])
        : "r"(a0), "r"(a1), "r"(a2), "r"(a3), "r"(b0), "r"(b1));
}

// ---------------------------------------------------------------------------
// Shared tf32 GEMM core: C[128,128] = W[128,128] * X[128,128]
// 8 warps (4x2): warp tile 32x64 = 2x8 m16n8k8 frags. K-tile = 32.
// As[d][k] pad 36, Bs[p][k] pad 36 -> conflict-free fragment LDS.
// acc layout per thread: acc[mf][nf][4]
// ---------------------------------------------------------------------------
struct GemmCtx {
    int lane, wm, wn;
};

__device__ __forceinline__ void gemm128_tf32(
    const float* __restrict__ wmat,   // W[d][k], row stride 128
    const float* __restrict__ xmat,   // X[k][p], row stride 256
    uint32_t (*As)[36], uint32_t (*Bs)[36],
    float acc[2][8][4], GemmCtx& cx)
{
    const int tid = threadIdx.x;
    const int lane = tid & 31, wid = tid >> 5;
    cx.lane = lane; cx.wm = wid >> 1; cx.wn = wid & 1;

    #pragma unroll
    for (int mf = 0; mf < 2; mf++)
        #pragma unroll
        for (int nf = 0; nf < 8; nf++)
            #pragma unroll
            for (int r = 0; r < 4; r++) acc[mf][nf][r] = 0.f;

    for (int kk = 0; kk < 128; kk += 32) {
        // fill As[d][k] (coalesced gmem read, conflict-free STS)
        #pragma unroll
        for (int i = 0; i < 16; i++) {
            int idx = tid + i * 256;       // 0..4095
            int d = idx >> 5, k = idx & 31;
            As[d][k] = f2tf32(wmat[d * 128 + kk + k]);
        }
        // fill Bs[p][k] (coalesced gmem read; 4-way STS conflict, minor)
        #pragma unroll
        for (int i = 0; i < 16; i++) {
            int idx = tid + i * 256;
            int p = idx & 127, k = idx >> 7;
            Bs[p][k] = f2tf32(xmat[(kk + k) * 256 + p]);
        }
        __syncthreads();

        #pragma unroll
        for (int ks = 0; ks < 32; ks += 8) {
            const int kq = lane & 3;
            // B fragments (col-major k x n): b0=B[k][n], b1=B[k+4][n]
            uint32_t bf[8][2];
            #pragma unroll
            for (int nf = 0; nf < 8; nf++) {
                int n = cx.wn * 64 + nf * 8 + (lane >> 2);
                bf[nf][0] = Bs[n][ks + kq];
                bf[nf][1] = Bs[n][ks + kq + 4];
            }
            #pragma unroll
            for (int mf = 0; mf < 2; mf++) {
                int m = cx.wm * 32 + mf * 16 + (lane >> 2);
                uint32_t a0 = As[m    ][ks + kq];
                uint32_t a1 = As[m + 8][ks + kq];
                uint32_t a2 = As[m    ][ks + kq + 4];
                uint32_t a3 = As[m + 8][ks + kq + 4];
                #pragma unroll
                for (int nf = 0; nf < 8; nf++)
                    mma_tf32(acc[mf][nf], a0, a1, a2, a3, bf[nf][0], bf[nf][1]);
            }
        }
        __syncthreads();
    }
}

// ---------------------------------------------------------------------------
// Kernel A: QKV projection -> scatter into per-head layout g_{q,k,v}[b][n][s][f]
// grid: (token 512, dtile 3, ptile 2), block 256
// ---------------------------------------------------------------------------
__global__ __launch_bounds__(256) void qkv_gemm(const float* __restrict__ seq,
                                                const float* __restrict__ w_qkv) {
    const int t  = blockIdx.x;
    const int dt = blockIdx.y;
    const int pt = blockIdx.z;

    __shared__ uint32_t As[128][36];
    __shared__ uint32_t Bs[128][36];

    float acc[2][8][4];
    GemmCtx cx;
    gemm128_tf32(w_qkv + dt * 16384,
                 seq + (size_t)t * 32768 + pt * 128,
                 As, Bs, acc, cx);

    // Epilogue: scatter into head layout.
    const int b_ = t >> 8, s_ = t & 255;
    float* dst = (dt == 0) ? g_q : (dt == 1) ? g_k : g_v;

    #pragma unroll
    for (int mf = 0; mf < 2; mf++) {
        #pragma unroll
        for (int half = 0; half < 2; half++) {   // row, row+8
            const int dl = cx.wm * 32 + mf * 16 + (cx.lane >> 2) + half * 8;
            const int ch = dl >> 6, cidx = dl & 63;
            #pragma unroll
            for (int nf = 0; nf < 8; nf++) {
                const int c0 = cx.wn * 64 + nf * 8 + 2 * (cx.lane & 3);
                const int p0 = pt * 128 + c0;
                const int Hi = p0 >> 4, Wi = p0 & 15;
                const int ys = Hi >> 3, hy = Hi & 7, xs = Wi >> 3, wx = Wi & 7;
                const int n = (ys * 2 + xs) * 2 + ch;
                const size_t base = ((size_t)((b_ * 8 + n) * 256 + s_)) * FDIM
                                  + cidx * 64 + hy * 8 + wx;
                float2 v = make_float2(acc[mf][nf][half * 2], acc[mf][nf][half * 2 + 1]);
                *reinterpret_cast<float2*>(dst + base) = v;
            }
        }
    }
}

// ---------------------------------------------------------------------------
// Kernel B: masked attention (fp32). One block (256 thr) per (b, head, query).
// ---------------------------------------------------------------------------
__global__ __launch_bounds__(256) void attn_kernel() {
    const int idx = blockIdx.x;
    const int i   = idx & 255;
    const int n   = (idx >> 8) & 7;
    const int b_  = idx >> 11;
    const int tid = threadIdx.x;

    const size_t slice = (size_t)(b_ * 8 + n) * SLICE;
    const size_t qb    = slice + (size_t)i * FDIM;

    float qreg[16];
    #pragma unroll
    for (int t = 0; t < 16; t++) qreg[t] = g_q[qb + t * 256 + tid];

    const int iy = i >> 4, ix = i & 15;
    int jidx[9]; int nj = 0;
    for (int dy = -1; dy <= 1; dy++) {
        int jy = iy + dy; if (jy < 0 || jy > 15) continue;
        for (int dx = -1; dx <= 1; dx++) {
            int jx = ix + dx; if (jx < 0 || jx > 15) continue;
            jidx[nj++] = jy * 16 + jx;
        }
    }

    float part[9];
    for (int jj = 0; jj < nj; jj++) {
        const float* kb = g_k + slice + (size_t)jidx[jj] * FDIM;
        float p = 0.f;
        #pragma unroll
        for (int t = 0; t < 16; t++) p += qreg[t] * kb[t * 256 + tid];
        part[jj] = p;
    }

    __shared__ float red[9][8];
    __shared__ float sm[9];
    for (int jj = 0; jj < nj; jj++) {
        float v = part[jj];
        #pragma unroll
        for (int o = 16; o > 0; o >>= 1) v += __shfl_down_sync(0xffffffffu, v, o);
        if ((tid & 31) == 0) red[jj][tid >> 5] = v;
    }
    __syncthreads();
    if (tid < nj) {
        float s = 0.f;
        #pragma unroll
        for (int w = 0; w < 8; w++) s += red[tid][w];
        sm[tid] = s * 0.015625f;
    }
    __syncthreads();

    float sc[9];
    float m = -1e30f;
    for (int jj = 0; jj < nj; jj++) { sc[jj] = sm[jj]; m = fmaxf(m, sc[jj]); }
    float sum = 0.f;
    for (int jj = 0; jj < nj; jj++) { sc[jj] = __expf(sc[jj] - m); sum += sc[jj]; }
    const float inv = 1.0f / sum;

    float facc[16];
    #pragma unroll
    for (int t = 0; t < 16; t++) facc[t] = 0.f;
    for (int jj = 0; jj < nj; jj++) {
        const float a = sc[jj] * inv;
        const float* vb = g_v + slice + (size_t)jidx[jj] * FDIM;
        #pragma unroll
        for (int t = 0; t < 16; t++) facc[t] += a * vb[t * 256 + tid];
    }

    const int ch = n & 1, sp = n >> 1, ys = sp >> 1, xs = sp & 1;
    const size_t tok = (size_t)(b_ * 256 + i) * 32768;
    #pragma unroll
    for (int t = 0; t < 16; t++) {
        const int f = t * 256 + tid;
        const int cidx = f >> 6, rem = f & 63, hy = rem >> 3, wx = rem & 7;
        const int Cc = ch * 64 + cidx;
        const int HWp = (ys * 8 + hy) * 16 + xs * 8 + wx;
        g_sa[tok + (size_t)Cc * 256 + HWp] = facc[t];
    }
}

// ---------------------------------------------------------------------------
// Kernel C: output projection + bias. grid: (token 512, ptile 2), block 256
// ---------------------------------------------------------------------------
__global__ __launch_bounds__(256) void out_gemm(const float* __restrict__ w_out,
                                                const float* __restrict__ b_out,
                                                float* __restrict__ out) {
    const int t  = blockIdx.x;
    const int pt = blockIdx.y;

    __shared__ uint32_t As[128][36];
    __shared__ uint32_t Bs[128][36];

    float acc[2][8][4];
    GemmCtx cx;
    gemm128_tf32(w_out,
                 g_sa + (size_t)t * 32768 + pt * 128,
                 As, Bs, acc, cx);

    // coalesced epilogue + bias, float2 stores
    #pragma unroll
    for (int mf = 0; mf < 2; mf++) {
        #pragma unroll
        for (int half = 0; half < 2; half++) {
            const int d = cx.wm * 32 + mf * 16 + (cx.lane >> 2) + half * 8;
            const float bias = b_out[d];
            #pragma unroll
            for (int nf = 0; nf < 8; nf++) {
                const int c0 = cx.wn * 64 + nf * 8 + 2 * (cx.lane & 3);
                float2 v = make_float2(acc[mf][nf][half * 2] + bias,
                                       acc[mf][nf][half * 2 + 1] + bias);
                *reinterpret_cast<float2*>(out + (size_t)t * 32768
                                           + (size_t)d * 256 + pt * 128 + c0) = v;
            }
        }
    }
}

extern "C" void kernel_launch(void* const* d_in, const int* in_sizes, int n_in,
                              void* d_out, int out_size) {
    const float* seq   = (const float*)d_in[0];
    const float* w_qkv = (const float*)d_in[1];
    const float* w_out = (const float*)d_in[2];
    const float* b_out = (const float*)d_in[3];
    float* out = (float*)d_out;

    dim3 gA(NTOK, 3, 2);
    qkv_gemm<<<gA, 256>>>(seq, w_qkv);

    attn_kernel<<<4096, 256>>>();

    dim3 gC(NTOK, 2);
    out_gemm<<<gC, 256>>>(w_out, b_out, out);
}